// round 5
// baseline (speedup 1.0000x reference)
#include <cuda_runtime.h>

// spixel_upsample2d: out[b, 4h+a, 4w+d] = sum_{c<2, ky<3, kx<3}
//     cv[b, c, h+ky-1, w+kx-1] * sp[b, c*9 + ky*3+kx, 4h+a, 4w+d]
// cv: (4,2,128,256) fp32 (1 MB, L2-resident)
// sp: (4,18,512,1024) fp32 (151 MB, streamed once)  out: (4,1,512,1024) fp32
//
// R4: one CTA per coarse row (b,h). Rows 4h..4h+3 share the same 18 patch
// values; per channel those 4 rows are 16KB contiguous -> better DRAM
// locality. Grid = 512 CTAs, 4 CTAs/SM -> exactly ONE uniform wave.

#define BB 4
#define CC 2
#define HH 128
#define WW 256
#define H4 512
#define W4 1024

__global__ __launch_bounds__(256, 4)
void spixel_up_kernel(const float* __restrict__ cv,
                      const float* __restrict__ sp,
                      float* __restrict__ out) {
    const int w  = threadIdx.x;              // coarse column 0..255
    const int bh = blockIdx.x;               // 0..511 = b*128 + h
    const int h  = bh & (HH - 1);            // coarse row
    const int b  = bh >> 7;                  // batch

    // ---- 18 patch values (shared by all 4 sub-rows and 4 sub-cols) ----
    float p[CC][9];
#pragma unroll
    for (int c = 0; c < CC; c++) {
        const float* __restrict__ xb = cv + ((size_t)(b * CC + c) * HH) * WW;
#pragma unroll
        for (int ky = 0; ky < 3; ky++) {
            const int hh = h + ky - 1;
            const bool hv = (hh >= 0) && (hh < HH);
#pragma unroll
            for (int kx = 0; kx < 3; kx++) {
                const int wwc = w + kx - 1;
                const bool v = hv && (wwc >= 0) && (wwc < WW);
                p[c][ky * 3 + kx] = v ? __ldg(&xb[(size_t)hh * WW + wwc]) : 0.0f;
            }
        }
    }

    const size_t ch_stride4 = (size_t)H4 * W4 / 4;   // 131072 float4 per channel
    const float4* __restrict__ sp4 =
        reinterpret_cast<const float4*>(sp) + (size_t)b * 18 * ch_stride4 + w;
    float4* __restrict__ out4 =
        reinterpret_cast<float4*>(out) + (size_t)b * H4 * (W4 / 4) + w;

    // ---- sweep the 4 sub-rows; 18 independent LDG.128 streams per row ----
#pragma unroll
    for (int a = 0; a < 4; a++) {
        const int y = 4 * h + a;
        const float4* __restrict__ row = sp4 + (size_t)y * (W4 / 4);

        float4 acc = make_float4(0.f, 0.f, 0.f, 0.f);
#pragma unroll
        for (int c = 0; c < CC; c++) {
#pragma unroll
            for (int k = 0; k < 9; k++) {
                const float4 s = row[(size_t)(c * 9 + k) * ch_stride4];
                const float v = p[c][k];
                acc.x = fmaf(v, s.x, acc.x);
                acc.y = fmaf(v, s.y, acc.y);
                acc.z = fmaf(v, s.z, acc.z);
                acc.w = fmaf(v, s.w, acc.w);
            }
        }
        out4[(size_t)y * (W4 / 4)] = acc;
    }
}

extern "C" void kernel_launch(void* const* d_in, const int* in_sizes, int n_in,
                              void* d_out, int out_size) {
    // Bind inputs by element count (robust to metadata ordering).
    const int CV_N = BB * CC * HH * WW;          // 262144
    const float* cv = nullptr;
    const float* sp = nullptr;
    for (int i = 0; i < n_in; i++) {
        if (in_sizes[i] == CV_N) cv = (const float*)d_in[i];
        else                     sp = (const float*)d_in[i];
    }
    float* out = (float*)d_out;

    dim3 grid(BB * HH);      // 512 CTAs: one per (batch, coarse row) -> 1 wave
    dim3 block(256);         // one thread per coarse column
    spixel_up_kernel<<<grid, block>>>(cv, sp, out);
}